// round 16
// baseline (speedup 1.0000x reference)
#include <cuda_runtime.h>
#include <cuda_fp16.h>
#include <cstdint>
#include <math.h>

#define BB 8
#define CC 64
#define HH 128
#define WW 128
#define HWD 16384
#define NS 3
#define K54 54
#define WSP2 20                     // per-scale weight pitch (floats) per tap
#define XSP 136                     // conv xs row pitch (floats)
#define CNT 131072.0f
#define BN_EPS 1e-5f

// ---------------- scratch (device globals; no runtime allocation) ----------
__device__ __half g_xH[BB * HWD * CC];         // x as [b][hw][c] fp16 (16.8 MB)
__device__ float g_off[BB * HWD * K54];        // offsets channel-last (28.3 MB)
__device__ float g_Wt[NS * CC * 9 * WSP2];     // Wp as [s][ci][tap][18 pad 20]
__device__ __half g_yH[NS * BB * CC * HWD];    // pre-BN y fp16 [s][b][o][hw] (50 MB)
__device__ float g_sum[NS * CC];
__device__ float g_sumsq[NS * CC];
__device__ float g_AB[NS * CC * 2];            // A = gamma*rsqrt(var+eps), B = beta-mu*A

// ---------------- cp.async helpers -----------------------------------------
__device__ __forceinline__ void cpa4z(unsigned s, const void* g) {
    asm volatile("cp.async.ca.shared.global [%0], [%1], 4, 0;" :: "r"(s), "l"(g));
}
__device__ __forceinline__ void cpa16(unsigned s, const void* g) {
    asm volatile("cp.async.cg.shared.global [%0], [%1], 16;" :: "r"(s), "l"(g));
}
__device__ __forceinline__ void cpa16p(unsigned s, const void* g, bool v) {
    asm volatile("cp.async.cg.shared.global [%0], [%1], 16, %2;"
                 :: "r"(s), "l"(g), "r"(v ? 16u : 0u));
}
__device__ __forceinline__ void cpa_commit() {
    asm volatile("cp.async.commit_group;");
}
template <int N>
__device__ __forceinline__ void cpa_wait() {
    asm volatile("cp.async.wait_group %0;" :: "n"(N));
}

// ---------------- k0: transpose x (b,c,hw) -> (b,hw,c) fp16 ----------------
__global__ void k_transpose(const float* __restrict__ x) {
    __shared__ float t[32][33];                // t[c_local][hw_local]
    int b = blockIdx.z;
    int hw0 = blockIdx.x * 32;
    int c0 = blockIdx.y * 32;
    int tx = threadIdx.x, ty = threadIdx.y;   // (32, 8)
    int tid = ty * 32 + tx;
#pragma unroll
    for (int j = 0; j < 4; j++)
        t[ty + 8 * j][tx] = x[(b * CC + c0 + ty + 8 * j) * HWD + hw0 + tx];
    __syncthreads();
    __half2* outp = (__half2*)g_xH;
#pragma unroll
    for (int idx = tid; idx < 512; idx += 256) {
        int hwl = idx >> 4, cp = idx & 15;
        __half2 v = __floats2half2_rn(t[2 * cp][hwl], t[2 * cp + 1][hwl]);
        outp[((size_t)(b * HWD + hw0 + hwl) * CC + c0) / 2 + cp] = v;
    }
}

// ---------------- k1: transpose Wp (per-scale, padded) + zero stats ---------
__global__ void k_prep(const float* __restrict__ Wp) {
    int idx = blockIdx.x * blockDim.x + threadIdx.x;
    if (idx < NS * CC * 9 * WSP2) {
        int s = idx / (CC * 9 * WSP2);
        int r = idx % (CC * 9 * WSP2);
        int ci = r / (9 * WSP2);
        int r2 = r % (9 * WSP2);
        int tap = r2 / WSP2;
        int k = r2 % WSP2;
        g_Wt[idx] = (k < 18) ? Wp[((s * 18 + k) * CC + ci) * 9 + tap] : 0.f;
    }
    if (idx < NS * CC) { g_sum[idx] = 0.f; g_sumsq[idx] = 0.f; }
}

// ---------------- k2: per-scale 3x3 conv, 1 row/block, 16B cp.async ---------
// block = 128 threads = one output row; 3 input rows staged (h-1..h+1).
// xs row layout: idx 3 = col -1 (zero), idx 4+c = col c, idx 132 = col 128 (zero).
__global__ void __launch_bounds__(128) k_conv(const float* __restrict__ x,
                                              const float* __restrict__ bp,
                                              int s) {
    __shared__ float xs[2][3 * XSP];   // double-buffered 3 rows
    __shared__ float ws[2][9 * WSP2];  // [tap][18 pad 20]
    int b = blockIdx.y;
    int h = blockIdx.x;
    int w = threadIdx.x;

    unsigned xs_s[2], ws_s[2];
    xs_s[0] = (unsigned)__cvta_generic_to_shared(&xs[0][0]);
    xs_s[1] = (unsigned)__cvta_generic_to_shared(&xs[1][0]);
    ws_s[0] = (unsigned)__cvta_generic_to_shared(&ws[0][0]);
    ws_s[1] = (unsigned)__cvta_generic_to_shared(&ws[1][0]);

    const float* xb = x + (size_t)b * CC * HWD;
    const float* wt = g_Wt + (size_t)s * CC * 9 * WSP2;

    // 3 rows x 34 tasks (102 total, single pass):
    // j<32 -> 16B interior chunk, j=32/33 -> zero halos
    auto prefetch = [&](int ci, int bi) {
        const float* xc = xb + (size_t)ci * HWD;
        if (w < 102) {
            int r = w / 34, j = w % 34;
            int hh = h - 1 + r;
            bool rok = (hh >= 0) & (hh < HH);
            const float* rowp = xc + min(max(hh, 0), HH - 1) * WW;
            unsigned rowd = xs_s[bi] + (unsigned)(r * XSP * 4);
            if (j < 32) cpa16p(rowd + 16 + j * 16, rowp + j * 4, rok);
            else if (j == 32) cpa4z(rowd + 12, rowp);       // col -1 -> 0
            else cpa4z(rowd + 528, rowp);                   // col 128 -> 0
        }
        if (w < 45)
            cpa16(ws_s[bi] + w * 16, wt + (size_t)ci * 9 * WSP2 + w * 4);
    };

    float acc[18];
#pragma unroll
    for (int k = 0; k < 18; k++) acc[k] = 0.f;

    prefetch(0, 0);
    cpa_commit();

    for (int ci = 0; ci < CC; ci++) {
        int bi = ci & 1;
        __syncthreads();
        if (ci + 1 < CC) {
            prefetch(ci + 1, bi ^ 1);
            cpa_commit();
            cpa_wait<1>();
        } else {
            cpa_wait<0>();
        }
        __syncthreads();

        float xv[9];
#pragma unroll
        for (int dh = 0; dh < 3; dh++)
#pragma unroll
            for (int dw = 0; dw < 3; dw++)
                xv[dh * 3 + dw] = xs[bi][dh * XSP + 3 + w + dw];
#pragma unroll
        for (int tap = 0; tap < 9; tap++) {
            float a = xv[tap];
            const float4* wr = (const float4*)&ws[bi][tap * WSP2];
#pragma unroll
            for (int k4 = 0; k4 < 4; k4++) {
                float4 wv = wr[k4];
                int k = k4 * 4;
                acc[k + 0] = fmaf(a, wv.x, acc[k + 0]);
                acc[k + 1] = fmaf(a, wv.y, acc[k + 1]);
                acc[k + 2] = fmaf(a, wv.z, acc[k + 2]);
                acc[k + 3] = fmaf(a, wv.w, acc[k + 3]);
            }
            acc[16] = fmaf(a, ws[bi][tap * WSP2 + 16], acc[16]);
            acc[17] = fmaf(a, ws[bi][tap * WSP2 + 17], acc[17]);
        }
    }
    float scale = (float)(s + 1);
    float* op = g_off + ((size_t)b * HWD + h * WW + w) * K54 + s * 18;
#pragma unroll
    for (int k = 0; k < 18; k++)
        op[k] = (acc[k] + bp[s * 18 + k]) * scale;
}

// ---------------- k3: gather + HFMA2 bilinear + GEMM + stats (one scale) ----
__global__ void __launch_bounds__(256, 3) k_gather(const float* __restrict__ WcG,
                                                   int s) {
    __shared__ float Wc_sh[64 * 64];      // [o][c]  (straight copy)
    __shared__ float xoff[32 * 68];       // [p][c] pitch 68
    __shared__ float off_sh[32 * 19];     // [p][18] pitch 19

    int h = blockIdx.x >> 2;
    int w0 = (blockIdx.x & 3) * 32;
    int b = blockIdx.y;
    int tid = threadIdx.x;

    {
        const float4* src = (const float4*)(WcG + s * 4096);
        float4* dst = (float4*)Wc_sh;
        for (int idx = tid; idx < 1024; idx += 256) dst[idx] = src[idx];
    }
    {
        const float* ob = g_off + ((size_t)(b * HWD + h * WW + w0)) * K54 + s * 18;
        for (int idx = tid; idx < 32 * 18; idx += 256) {
            int p = idx / 18, j = idx % 18;
            off_sh[p * 19 + j] = ob[p * K54 + j];
        }
    }
    __syncthreads();

    const __half* xHb = g_xH + (size_t)b * HWD * CC;
    const float inv9 = 1.f / 9.f;
    {
        int p = tid >> 3;                  // 0..31
        int l = tid & 7;                   // channel octet
        const float* offp = &off_sh[p * 19];

        int raws[9]; float fxs[9], fys[9];
#pragma unroll
        for (int n = 0; n < 9; n++) {
            float px = (float)(h + n / 3) + offp[n];
            float py = (float)(w0 + p + n % 3) + offp[9 + n];
            float flx = floorf(px), fly = floorf(py);
            fxs[n] = px - flx; fys[n] = py - fly;
            raws[n] = (int)(flx * 128.f + fly);
        }

        float acc[8];
#pragma unroll
        for (int j = 0; j < 8; j++) acc[j] = 0.f;
#pragma unroll
        for (int n = 0; n < 9; n++) {
            int raw = raws[n];
            float fx = fxs[n], fy = fys[n];
            __half2 wltH = __float2half2_rn((1.f - fx) * (1.f - fy));
            __half2 wrbH = __float2half2_rn(fx * fy);
            __half2 wlbH = __float2half2_rn((1.f - fx) * fy);
            __half2 wrtH = __float2half2_rn(fx * (1.f - fy));
            int i0 = min(max(raw, 0), HWD - 1);
            int i1 = min(max(raw + 1, 0), HWD - 1);
            int i2 = min(max(raw + 128, 0), HWD - 1);
            int i3 = min(max(raw + 129, 0), HWD - 1);
            uint4 v0 = *(const uint4*)(xHb + (size_t)i0 * CC + l * 8);
            uint4 v1 = *(const uint4*)(xHb + (size_t)i1 * CC + l * 8);
            uint4 v2 = *(const uint4*)(xHb + (size_t)i2 * CC + l * 8);
            uint4 v3 = *(const uint4*)(xHb + (size_t)i3 * CC + l * 8);
            const __half2* h0 = (const __half2*)&v0;
            const __half2* h1 = (const __half2*)&v1;
            const __half2* h2 = (const __half2*)&v2;
            const __half2* h3 = (const __half2*)&v3;
#pragma unroll
            for (int k = 0; k < 4; k++) {
                __half2 hv = __hmul2(h0[k], wltH);
                hv = __hfma2(h1[k], wlbH, hv);
                hv = __hfma2(h2[k], wrtH, hv);
                hv = __hfma2(h3[k], wrbH, hv);
                float2 f = __half22float2(hv);
                acc[2 * k + 0] += f.x;
                acc[2 * k + 1] += f.y;
            }
        }
        float4* xo = (float4*)&xoff[p * 68 + l * 8];
        xo[0] = make_float4(acc[0] * inv9, acc[1] * inv9, acc[2] * inv9, acc[3] * inv9);
        xo[1] = make_float4(acc[4] * inv9, acc[5] * inv9, acc[6] * inv9, acc[7] * inv9);
    }
    __syncthreads();

    int p2 = tid & 31;
    int obase = (tid >> 5) * 8;
    float acc2[8];
#pragma unroll
    for (int q = 0; q < 8; q++) acc2[q] = 0.f;
    for (int c4 = 0; c4 < 64; c4 += 4) {
        float4 xv = *(const float4*)&xoff[p2 * 68 + c4];
#pragma unroll
        for (int q = 0; q < 8; q++) {
            float4 wv = *(const float4*)&Wc_sh[(obase + q) * 64 + c4];  // broadcast
            acc2[q] = fmaf(xv.x, wv.x, acc2[q]);
            acc2[q] = fmaf(xv.y, wv.y, acc2[q]);
            acc2[q] = fmaf(xv.z, wv.z, acc2[q]);
            acc2[q] = fmaf(xv.w, wv.w, acc2[q]);
        }
    }
    __half* yb = g_yH + ((size_t)(s * BB + b) * CC) * HWD + h * WW + w0;
#pragma unroll
    for (int q = 0; q < 8; q++)
        yb[(size_t)(obase + q) * HWD + p2] = __float2half_rn(acc2[q]);

    int lane = tid & 31;
#pragma unroll
    for (int q = 0; q < 8; q++) {
        float v = acc2[q], v2 = v * v;
#pragma unroll
        for (int ofs = 16; ofs > 0; ofs >>= 1) {
            v += __shfl_down_sync(0xffffffffu, v, ofs);
            v2 += __shfl_down_sync(0xffffffffu, v2, ofs);
        }
        if (lane == 0) {
            atomicAdd(&g_sum[s * CC + obase + q], v);
            atomicAdd(&g_sumsq[s * CC + obase + q], v2);
        }
    }
}

// ---------------- k4: finalize BN coefficients ------------------------------
__global__ void k_stats(const float* __restrict__ gamma, const float* __restrict__ beta) {
    int t = threadIdx.x;
    if (t < NS * CC) {
        float inv = 1.f / CNT;
        float mu = g_sum[t] * inv;
        float var = g_sumsq[t] * inv - mu * mu;
        float A = gamma[t] * rsqrtf(var + BN_EPS);
        g_AB[t * 2] = A;
        g_AB[t * 2 + 1] = beta[t] - mu * A;
    }
}

// ---------------- k5: normalize + SiLU + average scales (4 elems/thread) ----
__global__ void k_final(float* __restrict__ out) {
    int idx4 = (blockIdx.x * blockDim.x + threadIdx.x) * 4;   // over B*C*HWD
    int o = (idx4 >> 14) & 63;
    float r[4] = {0.f, 0.f, 0.f, 0.f};
#pragma unroll
    for (int s = 0; s < NS; s++) {
        const __half2* zp = (const __half2*)(g_yH + (size_t)s * BB * CC * HWD + idx4);
        __half2 a = zp[0], bqh = zp[1];
        float2 f0 = __half22float2(a), f1 = __half22float2(bqh);
        int t = s * CC + o;
        float A = g_AB[t * 2], B = g_AB[t * 2 + 1];
        float vs[4] = {f0.x, f0.y, f1.x, f1.y};
#pragma unroll
        for (int j = 0; j < 4; j++) {
            float yn = fmaf(vs[j], A, B);
            r[j] += yn / (1.f + expf(-yn));
        }
    }
    *(float4*)(out + idx4) = make_float4(r[0] * (1.f / 3.f), r[1] * (1.f / 3.f),
                                         r[2] * (1.f / 3.f), r[3] * (1.f / 3.f));
}

// ---------------- launch: two-stream pipeline (R13 schedule) ----------------
// main: prep, conv0, gather0, gather1, gather2, stats, final
// side: transpose (|| conv0), then conv1, conv2 (|| gather0/1)
extern "C" void kernel_launch(void* const* d_in, const int* in_sizes, int n_in,
                              void* d_out, int out_size) {
    const float* x     = (const float*)d_in[0];
    const float* Wp    = (const float*)d_in[1];
    const float* bp    = (const float*)d_in[2];
    const float* Wc    = (const float*)d_in[3];
    const float* gamma = (const float*)d_in[4];
    const float* beta  = (const float*)d_in[5];
    float* out = (float*)d_out;

    static cudaStream_t sc = nullptr;
    static cudaEvent_t evP, evT, ev0, ev1, ev2;
    if (!sc) {
        cudaStreamCreateWithFlags(&sc, cudaStreamNonBlocking);
        cudaEventCreateWithFlags(&evP, cudaEventDisableTiming);
        cudaEventCreateWithFlags(&evT, cudaEventDisableTiming);
        cudaEventCreateWithFlags(&ev0, cudaEventDisableTiming);
        cudaEventCreateWithFlags(&ev1, cudaEventDisableTiming);
        cudaEventCreateWithFlags(&ev2, cudaEventDisableTiming);
    }

    dim3 tb(32, 8);
    dim3 tg(HWD / 32, CC / 32, BB);
    dim3 cg(HH, BB);                   // conv: 1 row/block
    dim3 gg(HH * 4, BB);

    k_prep<<<(NS * CC * 9 * WSP2 + 255) / 256, 256>>>(Wp);
    cudaEventRecord(evP, 0);

    // side: transpose runs concurrent with conv0
    cudaStreamWaitEvent(sc, evP, 0);
    k_transpose<<<tg, tb, 0, sc>>>(x);
    cudaEventRecord(evT, sc);

    k_conv<<<cg, 128>>>(x, bp, 0);
    cudaEventRecord(ev0, 0);

    cudaStreamWaitEvent(sc, ev0, 0);
    k_conv<<<cg, 128, 0, sc>>>(x, bp, 1);
    cudaEventRecord(ev1, sc);
    k_conv<<<cg, 128, 0, sc>>>(x, bp, 2);
    cudaEventRecord(ev2, sc);

    cudaStreamWaitEvent(0, evT, 0);
    k_gather<<<gg, 256>>>(Wc, 0);
    cudaStreamWaitEvent(0, ev1, 0);
    k_gather<<<gg, 256>>>(Wc, 1);
    cudaStreamWaitEvent(0, ev2, 0);
    k_gather<<<gg, 256>>>(Wc, 2);

    k_stats<<<1, 256>>>(gamma, beta);
    k_final<<<(BB * CC * HWD) / 1024, 256>>>(out);
}

// round 17
// speedup vs baseline: 1.1335x; 1.1335x over previous
#include <cuda_runtime.h>
#include <cuda_fp16.h>
#include <cstdint>
#include <math.h>

#define BB 8
#define CC 64
#define HH 128
#define WW 128
#define HWD 16384
#define NS 3
#define K54 54
#define WSP2 20                     // per-scale weight pitch (floats) per tap
#define XSP 136                     // conv xs row pitch (floats)
#define CNT 131072.0f
#define BN_EPS 1e-5f

// ---------------- scratch (device globals; no runtime allocation) ----------
__device__ __half g_xH[BB * HWD * CC];         // x as [b][hw][c] fp16 (16.8 MB)
__device__ float g_off[BB * HWD * K54];        // offsets channel-last (28.3 MB)
__device__ float g_Wt[NS * CC * 9 * WSP2];     // Wp as [s][ci][tap][18 pad 20]
__device__ __half g_yH[NS * BB * CC * HWD];    // pre-BN y fp16 [s][b][o][hw] (50 MB)
__device__ float g_sum[NS * CC];
__device__ float g_sumsq[NS * CC];
__device__ float g_AB[NS * CC * 2];            // A = gamma*rsqrt(var+eps), B = beta-mu*A

// ---------------- cp.async helpers -----------------------------------------
__device__ __forceinline__ void cpa4z(unsigned s, const void* g) {
    asm volatile("cp.async.ca.shared.global [%0], [%1], 4, 0;" :: "r"(s), "l"(g));
}
__device__ __forceinline__ void cpa16(unsigned s, const void* g) {
    asm volatile("cp.async.cg.shared.global [%0], [%1], 16;" :: "r"(s), "l"(g));
}
__device__ __forceinline__ void cpa16p(unsigned s, const void* g, bool v) {
    asm volatile("cp.async.cg.shared.global [%0], [%1], 16, %2;"
                 :: "r"(s), "l"(g), "r"(v ? 16u : 0u));
}
__device__ __forceinline__ void cpa_commit() {
    asm volatile("cp.async.commit_group;");
}
template <int N>
__device__ __forceinline__ void cpa_wait() {
    asm volatile("cp.async.wait_group %0;" :: "n"(N));
}

// ---------------- k0: transpose x (b,c,hw) -> (b,hw,c) fp16 ----------------
__global__ void k_transpose(const float* __restrict__ x) {
    __shared__ float t[32][33];                // t[c_local][hw_local]
    int b = blockIdx.z;
    int hw0 = blockIdx.x * 32;
    int c0 = blockIdx.y * 32;
    int tx = threadIdx.x, ty = threadIdx.y;   // (32, 8)
    int tid = ty * 32 + tx;
#pragma unroll
    for (int j = 0; j < 4; j++)
        t[ty + 8 * j][tx] = x[(b * CC + c0 + ty + 8 * j) * HWD + hw0 + tx];
    __syncthreads();
    __half2* outp = (__half2*)g_xH;
#pragma unroll
    for (int idx = tid; idx < 512; idx += 256) {
        int hwl = idx >> 4, cp = idx & 15;
        __half2 v = __floats2half2_rn(t[2 * cp][hwl], t[2 * cp + 1][hwl]);
        outp[((size_t)(b * HWD + hw0 + hwl) * CC + c0) / 2 + cp] = v;
    }
}

// ---------------- k1: transpose Wp (per-scale, padded) + zero stats ---------
__global__ void k_prep(const float* __restrict__ Wp) {
    int idx = blockIdx.x * blockDim.x + threadIdx.x;
    if (idx < NS * CC * 9 * WSP2) {
        int s = idx / (CC * 9 * WSP2);
        int r = idx % (CC * 9 * WSP2);
        int ci = r / (9 * WSP2);
        int r2 = r % (9 * WSP2);
        int tap = r2 / WSP2;
        int k = r2 % WSP2;
        g_Wt[idx] = (k < 18) ? Wp[((s * 18 + k) * CC + ci) * 9 + tap] : 0.f;
    }
    if (idx < NS * CC) { g_sum[idx] = 0.f; g_sumsq[idx] = 0.f; }
}

// ---------------- k2: per-scale 3x3 conv, 2 rows/block, 16B cp.async --------
// block = 128 threads; rows h0,h0+1; 4 input rows staged (h0-1..h0+2).
__global__ void __launch_bounds__(128) k_conv(const float* __restrict__ x,
                                              const float* __restrict__ bp,
                                              int s) {
    __shared__ float xs[2][4 * XSP];   // double-buffered 4 rows
    __shared__ float ws[2][9 * WSP2];  // [tap][18 pad 20]
    int b = blockIdx.y;
    int h0 = blockIdx.x * 2;
    int w = threadIdx.x;

    unsigned xs_s[2], ws_s[2];
    xs_s[0] = (unsigned)__cvta_generic_to_shared(&xs[0][0]);
    xs_s[1] = (unsigned)__cvta_generic_to_shared(&xs[1][0]);
    ws_s[0] = (unsigned)__cvta_generic_to_shared(&ws[0][0]);
    ws_s[1] = (unsigned)__cvta_generic_to_shared(&ws[1][0]);

    const float* xb = x + (size_t)b * CC * HWD;
    const float* wt = g_Wt + (size_t)s * CC * 9 * WSP2;

    // 4 rows x 34 tasks: j<32 -> 16B interior chunk, j=32/33 -> zero halos
    auto prefetch = [&](int ci, int bi) {
        const float* xc = xb + (size_t)ci * HWD;
#pragma unroll
        for (int it = 0; it < 2; it++) {
            int task = w + it * 128;
            if (task < 136) {
                int r = task / 34, j = task % 34;
                int hh = h0 - 1 + r;
                bool rok = (hh >= 0) & (hh < HH);
                const float* rowp = xc + min(max(hh, 0), HH - 1) * WW;
                unsigned rowd = xs_s[bi] + (unsigned)(r * XSP * 4);
                if (j < 32) cpa16p(rowd + 16 + j * 16, rowp + j * 4, rok);
                else if (j == 32) cpa4z(rowd + 12, rowp);       // col -1 -> 0
                else cpa4z(rowd + 528, rowp);                   // col 128 -> 0
            }
        }
        if (w < 45)
            cpa16(ws_s[bi] + w * 16, wt + (size_t)ci * 9 * WSP2 + w * 4);
    };

    float acc0[18], acc1[18];
#pragma unroll
    for (int k = 0; k < 18; k++) { acc0[k] = 0.f; acc1[k] = 0.f; }

    prefetch(0, 0);
    cpa_commit();

    for (int ci = 0; ci < CC; ci++) {
        int bi = ci & 1;
        __syncthreads();
        if (ci + 1 < CC) {
            prefetch(ci + 1, bi ^ 1);
            cpa_commit();
            cpa_wait<1>();
        } else {
            cpa_wait<0>();
        }
        __syncthreads();

        float xv0[9], xv1[9];
#pragma unroll
        for (int dh = 0; dh < 3; dh++)
#pragma unroll
            for (int dw = 0; dw < 3; dw++) {
                xv0[dh * 3 + dw] = xs[bi][dh * XSP + 3 + w + dw];
                xv1[dh * 3 + dw] = xs[bi][(dh + 1) * XSP + 3 + w + dw];
            }
#pragma unroll
        for (int tap = 0; tap < 9; tap++) {
            float a0 = xv0[tap], a1 = xv1[tap];
            const float4* wr = (const float4*)&ws[bi][tap * WSP2];
#pragma unroll
            for (int k4 = 0; k4 < 4; k4++) {
                float4 wv = wr[k4];
                int k = k4 * 4;
                acc0[k + 0] = fmaf(a0, wv.x, acc0[k + 0]);
                acc1[k + 0] = fmaf(a1, wv.x, acc1[k + 0]);
                acc0[k + 1] = fmaf(a0, wv.y, acc0[k + 1]);
                acc1[k + 1] = fmaf(a1, wv.y, acc1[k + 1]);
                acc0[k + 2] = fmaf(a0, wv.z, acc0[k + 2]);
                acc1[k + 2] = fmaf(a1, wv.z, acc1[k + 2]);
                acc0[k + 3] = fmaf(a0, wv.w, acc0[k + 3]);
                acc1[k + 3] = fmaf(a1, wv.w, acc1[k + 3]);
            }
            float w16 = ws[bi][tap * WSP2 + 16], w17 = ws[bi][tap * WSP2 + 17];
            acc0[16] = fmaf(a0, w16, acc0[16]);
            acc1[16] = fmaf(a1, w16, acc1[16]);
            acc0[17] = fmaf(a0, w17, acc0[17]);
            acc1[17] = fmaf(a1, w17, acc1[17]);
        }
    }
    float scale = (float)(s + 1);
    float* op0 = g_off + ((size_t)b * HWD + h0 * WW + w) * K54 + s * 18;
    float* op1 = op0 + (size_t)WW * K54;
#pragma unroll
    for (int k = 0; k < 18; k++) {
        float bk = bp[s * 18 + k];
        op0[k] = (acc0[k] + bk) * scale;
        op1[k] = (acc1[k] + bk) * scale;
    }
}

// ---------------- k3: gather + HFMA2 bilinear + GEMM + stats (one scale) ----
__global__ void __launch_bounds__(256, 3) k_gather(const float* __restrict__ WcG,
                                                   int s) {
    __shared__ float Wc_sh[64 * 64];      // [o][c]  (straight copy)
    __shared__ float xoff[32 * 68];       // [p][c] pitch 68
    __shared__ float off_sh[32 * 19];     // [p][18] pitch 19

    int h = blockIdx.x >> 2;
    int w0 = (blockIdx.x & 3) * 32;
    int b = blockIdx.y;
    int tid = threadIdx.x;

    {
        const float4* src = (const float4*)(WcG + s * 4096);
        float4* dst = (float4*)Wc_sh;
        for (int idx = tid; idx < 1024; idx += 256) dst[idx] = src[idx];
    }
    {
        const float* ob = g_off + ((size_t)(b * HWD + h * WW + w0)) * K54 + s * 18;
        for (int idx = tid; idx < 32 * 18; idx += 256) {
            int p = idx / 18, j = idx % 18;
            off_sh[p * 19 + j] = ob[p * K54 + j];
        }
    }
    __syncthreads();

    const __half* xHb = g_xH + (size_t)b * HWD * CC;
    const float inv9 = 1.f / 9.f;
    {
        int p = tid >> 3;                  // 0..31
        int l = tid & 7;                   // channel octet
        const float* offp = &off_sh[p * 19];

        int raws[9]; float fxs[9], fys[9];
#pragma unroll
        for (int n = 0; n < 9; n++) {
            float px = (float)(h + n / 3) + offp[n];
            float py = (float)(w0 + p + n % 3) + offp[9 + n];
            float flx = floorf(px), fly = floorf(py);
            fxs[n] = px - flx; fys[n] = py - fly;
            raws[n] = (int)(flx * 128.f + fly);
        }

        float acc[8];
#pragma unroll
        for (int j = 0; j < 8; j++) acc[j] = 0.f;
#pragma unroll
        for (int n = 0; n < 9; n++) {
            int raw = raws[n];
            float fx = fxs[n], fy = fys[n];
            __half2 wltH = __float2half2_rn((1.f - fx) * (1.f - fy));
            __half2 wrbH = __float2half2_rn(fx * fy);
            __half2 wlbH = __float2half2_rn((1.f - fx) * fy);
            __half2 wrtH = __float2half2_rn(fx * (1.f - fy));
            int i0 = min(max(raw, 0), HWD - 1);
            int i1 = min(max(raw + 1, 0), HWD - 1);
            int i2 = min(max(raw + 128, 0), HWD - 1);
            int i3 = min(max(raw + 129, 0), HWD - 1);
            uint4 v0 = *(const uint4*)(xHb + (size_t)i0 * CC + l * 8);
            uint4 v1 = *(const uint4*)(xHb + (size_t)i1 * CC + l * 8);
            uint4 v2 = *(const uint4*)(xHb + (size_t)i2 * CC + l * 8);
            uint4 v3 = *(const uint4*)(xHb + (size_t)i3 * CC + l * 8);
            const __half2* h0 = (const __half2*)&v0;
            const __half2* h1 = (const __half2*)&v1;
            const __half2* h2 = (const __half2*)&v2;
            const __half2* h3 = (const __half2*)&v3;
#pragma unroll
            for (int k = 0; k < 4; k++) {
                __half2 hv = __hmul2(h0[k], wltH);
                hv = __hfma2(h1[k], wlbH, hv);
                hv = __hfma2(h2[k], wrtH, hv);
                hv = __hfma2(h3[k], wrbH, hv);
                float2 f = __half22float2(hv);
                acc[2 * k + 0] += f.x;
                acc[2 * k + 1] += f.y;
            }
        }
        float4* xo = (float4*)&xoff[p * 68 + l * 8];
        xo[0] = make_float4(acc[0] * inv9, acc[1] * inv9, acc[2] * inv9, acc[3] * inv9);
        xo[1] = make_float4(acc[4] * inv9, acc[5] * inv9, acc[6] * inv9, acc[7] * inv9);
    }
    __syncthreads();

    int p2 = tid & 31;
    int obase = (tid >> 5) * 8;
    float acc2[8];
#pragma unroll
    for (int q = 0; q < 8; q++) acc2[q] = 0.f;
    for (int c4 = 0; c4 < 64; c4 += 4) {
        float4 xv = *(const float4*)&xoff[p2 * 68 + c4];
#pragma unroll
        for (int q = 0; q < 8; q++) {
            float4 wv = *(const float4*)&Wc_sh[(obase + q) * 64 + c4];  // broadcast
            acc2[q] = fmaf(xv.x, wv.x, acc2[q]);
            acc2[q] = fmaf(xv.y, wv.y, acc2[q]);
            acc2[q] = fmaf(xv.z, wv.z, acc2[q]);
            acc2[q] = fmaf(xv.w, wv.w, acc2[q]);
        }
    }
    __half* yb = g_yH + ((size_t)(s * BB + b) * CC) * HWD + h * WW + w0;
#pragma unroll
    for (int q = 0; q < 8; q++)
        yb[(size_t)(obase + q) * HWD + p2] = __float2half_rn(acc2[q]);

    int lane = tid & 31;
#pragma unroll
    for (int q = 0; q < 8; q++) {
        float v = acc2[q], v2 = v * v;
#pragma unroll
        for (int ofs = 16; ofs > 0; ofs >>= 1) {
            v += __shfl_down_sync(0xffffffffu, v, ofs);
            v2 += __shfl_down_sync(0xffffffffu, v2, ofs);
        }
        if (lane == 0) {
            atomicAdd(&g_sum[s * CC + obase + q], v);
            atomicAdd(&g_sumsq[s * CC + obase + q], v2);
        }
    }
}

// ---------------- k4: finalize BN coefficients ------------------------------
__global__ void k_stats(const float* __restrict__ gamma, const float* __restrict__ beta) {
    int t = threadIdx.x;
    if (t < NS * CC) {
        float inv = 1.f / CNT;
        float mu = g_sum[t] * inv;
        float var = g_sumsq[t] * inv - mu * mu;
        float A = gamma[t] * rsqrtf(var + BN_EPS);
        g_AB[t * 2] = A;
        g_AB[t * 2 + 1] = beta[t] - mu * A;
    }
}

// ---------------- k5: normalize + SiLU + average scales (4 elems/thread) ----
__global__ void k_final(float* __restrict__ out) {
    int idx4 = (blockIdx.x * blockDim.x + threadIdx.x) * 4;   // over B*C*HWD
    int o = (idx4 >> 14) & 63;
    float r[4] = {0.f, 0.f, 0.f, 0.f};
#pragma unroll
    for (int s = 0; s < NS; s++) {
        const __half2* zp = (const __half2*)(g_yH + (size_t)s * BB * CC * HWD + idx4);
        __half2 a = zp[0], bqh = zp[1];
        float2 f0 = __half22float2(a), f1 = __half22float2(bqh);
        int t = s * CC + o;
        float A = g_AB[t * 2], B = g_AB[t * 2 + 1];
        float vs[4] = {f0.x, f0.y, f1.x, f1.y};
#pragma unroll
        for (int j = 0; j < 4; j++) {
            float yn = fmaf(vs[j], A, B);
            r[j] += yn / (1.f + expf(-yn));
        }
    }
    *(float4*)(out + idx4) = make_float4(r[0] * (1.f / 3.f), r[1] * (1.f / 3.f),
                                         r[2] * (1.f / 3.f), r[3] * (1.f / 3.f));
}

// ---------------- launch: two-stream pipeline (R13 schedule) ----------------
// main: prep, conv0, gather0, gather1, gather2, stats, final
// side: transpose (|| conv0), then conv1, conv2 (|| gather0/1)
extern "C" void kernel_launch(void* const* d_in, const int* in_sizes, int n_in,
                              void* d_out, int out_size) {
    const float* x     = (const float*)d_in[0];
    const float* Wp    = (const float*)d_in[1];
    const float* bp    = (const float*)d_in[2];
    const float* Wc    = (const float*)d_in[3];
    const float* gamma = (const float*)d_in[4];
    const float* beta  = (const float*)d_in[5];
    float* out = (float*)d_out;

    static cudaStream_t sc = nullptr;
    static cudaEvent_t evP, evT, ev0, ev1, ev2;
    if (!sc) {
        cudaStreamCreateWithFlags(&sc, cudaStreamNonBlocking);
        cudaEventCreateWithFlags(&evP, cudaEventDisableTiming);
        cudaEventCreateWithFlags(&evT, cudaEventDisableTiming);
        cudaEventCreateWithFlags(&ev0, cudaEventDisableTiming);
        cudaEventCreateWithFlags(&ev1, cudaEventDisableTiming);
        cudaEventCreateWithFlags(&ev2, cudaEventDisableTiming);
    }

    dim3 tb(32, 8);
    dim3 tg(HWD / 32, CC / 32, BB);
    dim3 cg(HH / 2, BB);               // conv: 2 rows/block
    dim3 gg(HH * 4, BB);

    k_prep<<<(NS * CC * 9 * WSP2 + 255) / 256, 256>>>(Wp);
    cudaEventRecord(evP, 0);

    // side: transpose runs concurrent with conv0
    cudaStreamWaitEvent(sc, evP, 0);
    k_transpose<<<tg, tb, 0, sc>>>(x);
    cudaEventRecord(evT, sc);

    k_conv<<<cg, 128>>>(x, bp, 0);
    cudaEventRecord(ev0, 0);

    cudaStreamWaitEvent(sc, ev0, 0);
    k_conv<<<cg, 128, 0, sc>>>(x, bp, 1);
    cudaEventRecord(ev1, sc);
    k_conv<<<cg, 128, 0, sc>>>(x, bp, 2);
    cudaEventRecord(ev2, sc);

    cudaStreamWaitEvent(0, evT, 0);
    k_gather<<<gg, 256>>>(Wc, 0);
    cudaStreamWaitEvent(0, ev1, 0);
    k_gather<<<gg, 256>>>(Wc, 1);
    cudaStreamWaitEvent(0, ev2, 0);
    k_gather<<<gg, 256>>>(Wc, 2);

    k_stats<<<1, 256>>>(gamma, beta);
    k_final<<<(BB * CC * HWD) / 1024, 256>>>(out);
}